// round 5
// baseline (speedup 1.0000x reference)
#include <cuda_runtime.h>
#include <cuda_bf16.h>
#include <math.h>
#include <stdint.h>

// Problem dims (fixed)
#define BB 8
#define MM 2048
#define DD 1024
#define HALF_D 512
#define ROWS 16384           // BB*MM
#define K3P 3072             // 3*DD  (split-K for K=1024 GEMMs)
#define K3S 6144             // 3*MM  (split-K for PV GEMM, K=2048)

// ---------------------------------------------------------------------------
// Device-global scratch (allocation-free, graph-capture safe)
// ---------------------------------------------------------------------------
__device__ __nv_bfloat16 g_x3[(size_t)ROWS * K3P];       // x  split, A-side
__device__ __nv_bfloat16 g_w3[(size_t)(3 * DD) * K3P];   // [wq;wk;wv] split, B-side
__device__ float g_Vf[(size_t)ROWS * DD];
__device__ __nv_bfloat16 g_Q3[(size_t)ROWS * K3P];       // rotated Q split, A-side
__device__ __nv_bfloat16 g_K3[(size_t)ROWS * K3P];       // rotated K split, B-side
__device__ __nv_bfloat16 g_V3T[(size_t)BB * DD * K3S];   // V^T split, B-side
__device__ float g_Sf[(size_t)BB * MM * MM];             // scores fp32
__device__ __nv_bfloat16 g_S3[(size_t)BB * MM * K3S];    // attn split, A-side
__device__ float g_cos[(size_t)MM * HALF_D];
__device__ float g_sin[(size_t)MM * HALF_D];

// ---------------------------------------------------------------------------
// PTX helpers (base-ISA: mma.sync / ldmatrix / cp.async)
// ---------------------------------------------------------------------------
__device__ __forceinline__ uint32_t smem_u32(const void* p) {
    uint32_t a;
    asm("{ .reg .u64 t; cvta.to.shared.u64 t, %1; cvt.u32.u64 %0, t; }" : "=r"(a) : "l"(p));
    return a;
}
__device__ __forceinline__ void mma16816(float* d, const uint32_t* a, const uint32_t* b) {
    asm volatile(
        "mma.sync.aligned.m16n8k16.row.col.f32.bf16.bf16.f32 "
        "{%0,%1,%2,%3}, {%4,%5,%6,%7}, {%8,%9}, {%0,%1,%2,%3};"
        : "+f"(d[0]), "+f"(d[1]), "+f"(d[2]), "+f"(d[3])
        : "r"(a[0]), "r"(a[1]), "r"(a[2]), "r"(a[3]), "r"(b[0]), "r"(b[1]));
}
__device__ __forceinline__ void ldsm4(uint32_t* r, uint32_t addr) {
    asm volatile("ldmatrix.sync.aligned.m8n8.x4.shared.b16 {%0,%1,%2,%3}, [%4];"
                 : "=r"(r[0]), "=r"(r[1]), "=r"(r[2]), "=r"(r[3]) : "r"(addr));
}
__device__ __forceinline__ void cpasync16(uint32_t dst, const void* src) {
    asm volatile("cp.async.cg.shared.global [%0], [%1], 16;" :: "r"(dst), "l"(src));
}
__device__ __forceinline__ void cp_commit() {
    asm volatile("cp.async.commit_group;" ::: "memory");
}
template <int N>
__device__ __forceinline__ void cp_wait() {
    asm volatile("cp.async.wait_group %0;" :: "n"(N) : "memory");
}

// ---------------------------------------------------------------------------
// bf16 split helpers
// ---------------------------------------------------------------------------
__device__ __forceinline__ void split_bf16(float f, __nv_bfloat16& hi, __nv_bfloat16& lo) {
    hi = __float2bfloat16(f);
    lo = __float2bfloat16(f - __bfloat162float(hi));
}

// ---------------------------------------------------------------------------
// RoPE tables
// ---------------------------------------------------------------------------
__global__ void rope_tables_kernel() {
    int idx = blockIdx.x * blockDim.x + threadIdx.x;
    if (idx >= MM * HALF_D) return;
    int m = idx / HALF_D;
    int i = idx % HALF_D;
    double theta_d = pow(10000.0, -2.0 * ((double)i - 1.0) / (double)DD);
    float ang = (float)m * (float)theta_d;
    g_cos[idx] = cosf(ang);
    g_sin[idx] = sinf(ang);
}

// ---------------------------------------------------------------------------
// fp32 -> 3-segment bf16 split (A-side [hi,lo,hi]) for x
// ---------------------------------------------------------------------------
__global__ void cvt3_x_kernel(const float* __restrict__ src, __nv_bfloat16* __restrict__ dst) {
    long idx = (long)blockIdx.x * blockDim.x + threadIdx.x;
    if (idx >= (long)ROWS * DD) return;
    long row = idx / DD;
    int k = (int)(idx % DD);
    __nv_bfloat16 hi, lo;
    split_bf16(src[idx], hi, lo);
    __nv_bfloat16* r = dst + row * (long)K3P;
    r[k] = hi;
    r[DD + k] = lo;
    r[2 * DD + k] = hi;
}

// ---------------------------------------------------------------------------
// All three weights -> B-side split [hi,hi,lo] in one launch (z selects w)
// ---------------------------------------------------------------------------
__global__ void cvt3_w_kernel(const float* __restrict__ wq, const float* __restrict__ wk,
                              const float* __restrict__ wv, __nv_bfloat16* __restrict__ dst) {
    long idx = (long)blockIdx.x * blockDim.x + threadIdx.x;
    if (idx >= (long)DD * DD) return;
    const float* src = blockIdx.z == 0 ? wq : (blockIdx.z == 1 ? wk : wv);
    long row = idx / DD;
    int k = (int)(idx % DD);
    __nv_bfloat16 hi, lo;
    split_bf16(src[idx], hi, lo);
    __nv_bfloat16* r = dst + ((long)blockIdx.z * DD + row) * (long)K3P;
    r[k] = hi;
    r[DD + k] = hi;
    r[2 * DD + k] = lo;
}

// ---------------------------------------------------------------------------
// V [b*MM + k][n] -> V3T [b*DD + n][seg*MM + k]  (transpose + split, B-side)
// ---------------------------------------------------------------------------
__global__ void vT_cvt_kernel(const float* __restrict__ V, __nv_bfloat16* __restrict__ V3T) {
    __shared__ float ts[32][33];
    int b = blockIdx.z;
    int n0 = blockIdx.x * 32, k0 = blockIdx.y * 32;
    int tx = threadIdx.x, ty = threadIdx.y;  // 32 x 8
#pragma unroll
    for (int i = 0; i < 4; i++) {
        int k = k0 + ty + i * 8;
        ts[ty + i * 8][tx] = V[((long)(b * MM + k)) * DD + n0 + tx];
    }
    __syncthreads();
#pragma unroll
    for (int i = 0; i < 4; i++) {
        int n = n0 + ty + i * 8;
        float f = ts[tx][ty + i * 8];
        __nv_bfloat16 hi, lo;
        split_bf16(f, hi, lo);
        __nv_bfloat16* r = V3T + ((long)(b * DD + n)) * K3S;
        int k = k0 + tx;
        r[k] = hi;
        r[MM + k] = hi;
        r[2 * MM + k] = lo;
    }
}

// ---------------------------------------------------------------------------
// Row softmax (len MM) fused with A-side split conversion
// ---------------------------------------------------------------------------
__global__ void __launch_bounds__(256) softmax_cvt_kernel(const float* __restrict__ S,
                                                          __nv_bfloat16* __restrict__ S3) {
    __shared__ float red[256];
    long row = blockIdx.x;
    const float4* p = reinterpret_cast<const float4*>(S + row * (long)MM);
    int t = threadIdx.x;
    float4 v0 = p[t];
    float4 v1 = p[t + 256];

    float mx = fmaxf(fmaxf(fmaxf(v0.x, v0.y), fmaxf(v0.z, v0.w)),
                     fmaxf(fmaxf(v1.x, v1.y), fmaxf(v1.z, v1.w)));
    red[t] = mx;
    __syncthreads();
    for (int s = 128; s > 0; s >>= 1) {
        if (t < s) red[t] = fmaxf(red[t], red[t + s]);
        __syncthreads();
    }
    mx = red[0];
    __syncthreads();

    v0.x = expf(v0.x - mx); v0.y = expf(v0.y - mx);
    v0.z = expf(v0.z - mx); v0.w = expf(v0.w - mx);
    v1.x = expf(v1.x - mx); v1.y = expf(v1.y - mx);
    v1.z = expf(v1.z - mx); v1.w = expf(v1.w - mx);

    float sum = (v0.x + v0.y + v0.z + v0.w) + (v1.x + v1.y + v1.z + v1.w);
    red[t] = sum;
    __syncthreads();
    for (int s = 128; s > 0; s >>= 1) {
        if (t < s) red[t] += red[t + s];
        __syncthreads();
    }
    float inv = 1.0f / red[0];
    __syncthreads();

    __nv_bfloat16* r = S3 + row * (long)K3S;
    float f[8] = {v0.x * inv, v0.y * inv, v0.z * inv, v0.w * inv,
                  v1.x * inv, v1.y * inv, v1.z * inv, v1.w * inv};
    int cb[2] = {4 * t, 1024 + 4 * t};
#pragma unroll
    for (int h = 0; h < 2; h++) {
#pragma unroll
        for (int j = 0; j < 4; j += 2) {
            __nv_bfloat16 h0, l0, h1, l1;
            split_bf16(f[h * 4 + j], h0, l0);
            split_bf16(f[h * 4 + j + 1], h1, l1);
            int k = cb[h] + j;
            *reinterpret_cast<__nv_bfloat162*>(r + k)          = __halves2bfloat162(h0, h1);
            *reinterpret_cast<__nv_bfloat162*>(r + MM + k)     = __halves2bfloat162(l0, l1);  // lo (A-side)
            *reinterpret_cast<__nv_bfloat162*>(r + 2 * MM + k) = __halves2bfloat162(h0, h1);
        }
    }
}

// ---------------------------------------------------------------------------
// mma.sync bf16 GEMM (NT, both operands K-major), 128x128 CTA tile, BK=64,
// 3-stage cp.async pipeline, XOR-swizzled smem.
// 4 warps (2M x 2N), 64x64 warp tile: per k16-step 8 LDSM.x4 : 32 HMMA.
//   EPI=0: C[m,n] = alpha * A x B^T   (fp32 store)
//   EPI=1: merged QKV projection epilogue with fused RoPE + split
// ---------------------------------------------------------------------------
#define BKC 64                     // K per chunk (bf16 elems)
#define TILE_BYTES (128 * BKC * 2) // 16 KB per operand tile
#define GEMM_SMEM (6 * TILE_BYTES) // 3 stages x (A+B) = 96 KB

template <int EPI>
__global__ void __launch_bounds__(128, 2) mma_gemm_kernel(
    const __nv_bfloat16* __restrict__ A, const __nv_bfloat16* __restrict__ B,
    float* __restrict__ C, int K3, int ldc, long sA, long sB, long sC, float alpha)
{
    extern __shared__ char smem[];
    const uint32_t sb = smem_u32(smem);
    const int tid = threadIdx.x;
    const int wid = tid >> 5, lane = tid & 31;
    const int wm = wid & 1;          // warp M index (x64 rows)
    const int wn = wid >> 1;         // warp N index (x64 cols)

    const long row0 = (long)blockIdx.y * 128;
    const long col0 = (long)blockIdx.x * 128;
    const __nv_bfloat16* Abase = A + blockIdx.z * sA + row0 * K3;
    const __nv_bfloat16* Bbase = B + blockIdx.z * sB + col0 * K3;
    float* Cbase = C + blockIdx.z * sC;

    const int ldRow = tid >> 3;      // rows 0..15 (+16*i)
    const int ldC = tid & 7;         // 16B chunk within 128B row

    float acc[4][8][4];
#pragma unroll
    for (int i = 0; i < 4; i++)
#pragma unroll
        for (int j = 0; j < 8; j++)
#pragma unroll
            for (int q = 0; q < 4; q++) acc[i][j][q] = 0.0f;

    const int nch = K3 >> 6;

    auto load_tile = [&](int ch, int buf) {
        const long k0 = (long)ch << 6;
        const uint32_t sbA = sb + buf * 2 * TILE_BYTES;
        const uint32_t sbB = sbA + TILE_BYTES;
#pragma unroll
        for (int i = 0; i < 8; i++) {
            int row = ldRow + i * 16;
            int c = ldC;
            uint32_t off = ((uint32_t)row * 8u + (uint32_t)(c ^ (row & 7))) * 16u;
            cpasync16(sbA + off, Abase + (long)row * K3 + k0 + c * 8);
            cpasync16(sbB + off, Bbase + (long)row * K3 + k0 + c * 8);
        }
    };

    load_tile(0, 0);
    cp_commit();
    load_tile(1, 1);
    cp_commit();

    for (int ch = 0; ch < nch; ch++) {
        if (ch + 2 < nch) {
            load_tile(ch + 2, (ch + 2) % 3);
            cp_commit();
            cp_wait<2>();
        } else if (ch + 1 < nch) {
            cp_wait<1>();
        } else {
            cp_wait<0>();
        }
        __syncthreads();

        const uint32_t sbA = sb + (ch % 3) * 2 * TILE_BYTES;
        const uint32_t sbB = sbA + TILE_BYTES;

#pragma unroll
        for (int ks = 0; ks < 4; ks++) {             // 4 k16 steps in BK=64
            uint32_t a[4][4];
            uint32_t b[8][2];
#pragma unroll
            for (int mt = 0; mt < 4; mt++) {
                int row = wm * 64 + mt * 16 + (lane & 15);
                int c = 2 * ks + (lane >> 4);
                uint32_t addr = sbA + ((uint32_t)row * 8u + (uint32_t)(c ^ (row & 7))) * 16u;
                ldsm4(a[mt], addr);
            }
#pragma unroll
            for (int p = 0; p < 4; p++) {
                int row = wn * 64 + p * 16 + (lane & 15);
                int c = 2 * ks + (lane >> 4);
                uint32_t addr = sbB + ((uint32_t)row * 8u + (uint32_t)(c ^ (row & 7))) * 16u;
                uint32_t r[4];
                ldsm4(r, addr);
                b[2 * p][0] = r[0]; b[2 * p][1] = r[2];
                b[2 * p + 1][0] = r[1]; b[2 * p + 1][1] = r[3];
            }
#pragma unroll
            for (int mt = 0; mt < 4; mt++)
#pragma unroll
                for (int nt = 0; nt < 8; nt++)
                    mma16816(acc[mt][nt], a[mt], b[nt]);
        }
        __syncthreads();
    }

    // ---- epilogue ----
    const int g = lane >> 2, tg = lane & 3;
    if (EPI == 0) {
#pragma unroll
        for (int mt = 0; mt < 4; mt++) {
            long r0 = row0 + wm * 64 + mt * 16 + g;
#pragma unroll
            for (int nt = 0; nt < 8; nt++) {
                long cc = col0 + wn * 64 + nt * 8 + tg * 2;
                float2 v0 = make_float2(alpha * acc[mt][nt][0], alpha * acc[mt][nt][1]);
                float2 v1 = make_float2(alpha * acc[mt][nt][2], alpha * acc[mt][nt][3]);
                *reinterpret_cast<float2*>(Cbase + r0 * ldc + cc) = v0;
                *reinterpret_cast<float2*>(Cbase + (r0 + 8) * ldc + cc) = v1;
            }
        }
    } else {
        // merged QKV epilogue. n in [0,3072): Q | K | V
        const int nbase = (int)col0 + wn * 64 + tg * 2;
#pragma unroll
        for (int mt = 0; mt < 4; mt++) {
            long r0 = row0 + wm * 64 + mt * 16 + g;   // global row (+8 for second half)
#pragma unroll
            for (int nt = 0; nt < 8; nt++) {
                int n = nbase + nt * 8;
                if (n < 2048) {
                    // RoPE + 3-seg split
                    int k = n & 1023;                 // col within Q or K block
                    int pidx = k >> 1;
#pragma unroll
                    for (int h = 0; h < 2; h++) {
                        long r = r0 + h * 8;
                        int m = (int)(r & (MM - 1));
                        float c = g_cos[(size_t)m * HALF_D + pidx];
                        float s = g_sin[(size_t)m * HALF_D + pidx];
                        float e = acc[mt][nt][2 * h], o = acc[mt][nt][2 * h + 1];
                        float re = e * c + o * s;
                        float ro = -e * s + o * c;
                        __nv_bfloat16 he, le, ho, lo;
                        split_bf16(re, he, le);
                        split_bf16(ro, ho, lo);
                        __nv_bfloat16* dst = (n < 1024 ? g_Q3 : g_K3) + r * (long)K3P + k;
                        __nv_bfloat162 hi2 = __halves2bfloat162(he, ho);
                        __nv_bfloat162 lo2 = __halves2bfloat162(le, lo);
                        // Q (A-side): [hi,lo,hi]   K (B-side): [hi,hi,lo]
                        *reinterpret_cast<__nv_bfloat162*>(dst) = hi2;
                        *reinterpret_cast<__nv_bfloat162*>(dst + DD) = (n < 1024) ? lo2 : hi2;
                        *reinterpret_cast<__nv_bfloat162*>(dst + 2 * DD) = (n < 1024) ? hi2 : lo2;
                    }
                } else {
                    int k = n - 2048;
                    float2 v0 = make_float2(acc[mt][nt][0], acc[mt][nt][1]);
                    float2 v1 = make_float2(acc[mt][nt][2], acc[mt][nt][3]);
                    *reinterpret_cast<float2*>(g_Vf + r0 * DD + k) = v0;
                    *reinterpret_cast<float2*>(g_Vf + (r0 + 8) * DD + k) = v1;
                }
            }
        }
    }
}

// ---------------------------------------------------------------------------
// Launch.  Order puts the scores GEMM at launch index 5 so the ncu capture
// (-s 5 -c 1) profiles it.
// ---------------------------------------------------------------------------
extern "C" void kernel_launch(void* const* d_in, const int* in_sizes, int n_in,
                              void* d_out, int out_size) {
    (void)in_sizes; (void)n_in; (void)out_size;
    const float* x  = (const float*)d_in[0];
    const float* wq = (const float*)d_in[1];
    const float* wk = (const float*)d_in[2];
    const float* wv = (const float*)d_in[3];
    float* out = (float*)d_out;

    __nv_bfloat16 *x3, *w3, *Q3, *K3, *V3T, *S3;
    float *Vf, *Sf;
    cudaGetSymbolAddress((void**)&x3, g_x3);
    cudaGetSymbolAddress((void**)&w3, g_w3);
    cudaGetSymbolAddress((void**)&Vf, g_Vf);
    cudaGetSymbolAddress((void**)&Q3, g_Q3);
    cudaGetSymbolAddress((void**)&K3, g_K3);
    cudaGetSymbolAddress((void**)&V3T, g_V3T);
    cudaGetSymbolAddress((void**)&Sf, g_Sf);
    cudaGetSymbolAddress((void**)&S3, g_S3);

    cudaFuncSetAttribute(mma_gemm_kernel<0>, cudaFuncAttributeMaxDynamicSharedMemorySize, GEMM_SMEM);
    cudaFuncSetAttribute(mma_gemm_kernel<1>, cudaFuncAttributeMaxDynamicSharedMemorySize, GEMM_SMEM);

    // 0: RoPE tables
    rope_tables_kernel<<<(MM * HALF_D + 255) / 256, 256>>>();
    // 1: x -> split
    cvt3_x_kernel<<<(int)(((long)ROWS * DD + 255) / 256), 256>>>(x, x3);
    // 2: all weights -> split
    dim3 gW((DD * DD + 255) / 256, 1, 3);
    cvt3_w_kernel<<<gW, 256>>>(wq, wk, wv, w3);

    // 3: Merged QKV projection with fused RoPE/split epilogue
    dim3 gProj(3 * DD / 128, ROWS / 128, 1);
    mma_gemm_kernel<1><<<gProj, 128, GEMM_SMEM>>>(x3, w3, nullptr, K3P, 0, 0, 0, 0, 1.0f);

    // 4: V transpose + split
    dim3 gV(DD / 32, MM / 32, BB);
    vT_cvt_kernel<<<gV, dim3(32, 8)>>>(Vf, V3T);

    // 5: scores = Qr @ Kr^T / 32   <- ncu capture target
    dim3 gScore(MM / 128, MM / 128, BB);
    mma_gemm_kernel<0><<<gScore, 128, GEMM_SMEM>>>(Q3, K3, Sf, K3P, MM,
                                                   (long)MM * K3P, (long)MM * K3P,
                                                   (long)MM * MM, 0.03125f);

    // 6: softmax + split
    softmax_cvt_kernel<<<BB * MM, 256>>>(Sf, S3);

    // 7: out = attn @ V
    dim3 gOut(DD / 128, MM / 128, BB);
    mma_gemm_kernel<0><<<gOut, 128, GEMM_SMEM>>>(S3, V3T, out, K3S, DD,
                                                 (long)MM * K3S, (long)DD * K3S,
                                                 (long)MM * DD, 1.0f);
}

// round 6
// speedup vs baseline: 1.0114x; 1.0114x over previous
#include <cuda_runtime.h>
#include <cuda_bf16.h>
#include <math.h>
#include <stdint.h>

// Problem dims (fixed)
#define BB 8
#define MM 2048
#define DD 1024
#define HALF_D 512
#define ROWS 16384           // BB*MM
#define K3P 3072             // 3*DD  (split-K for K=1024 GEMMs)
#define K3S 6144             // 3*MM  (split-K for PV GEMM, K=2048)

// ---------------------------------------------------------------------------
// Device-global scratch (allocation-free, graph-capture safe)
// ---------------------------------------------------------------------------
__device__ __nv_bfloat16 g_x3[(size_t)ROWS * K3P];       // x  split, A-side
__device__ __nv_bfloat16 g_w3[(size_t)(3 * DD) * K3P];   // [wq;wk;wv] split, B-side
__device__ float g_Vf[(size_t)ROWS * DD];
__device__ __nv_bfloat16 g_Q3[(size_t)ROWS * K3P];       // rotated Q split, A-side
__device__ __nv_bfloat16 g_K3[(size_t)ROWS * K3P];       // rotated K split, B-side
__device__ __nv_bfloat16 g_V3T[(size_t)BB * DD * K3S];   // V^T split, B-side
__device__ float g_Sf[(size_t)BB * MM * MM];             // scores fp32
__device__ __nv_bfloat16 g_S3[(size_t)BB * MM * K3S];    // attn split, A-side
__device__ float g_cos[(size_t)MM * HALF_D];
__device__ float g_sin[(size_t)MM * HALF_D];

// ---------------------------------------------------------------------------
// PTX helpers (base-ISA: mma.sync / ldmatrix / cp.async)
// ---------------------------------------------------------------------------
__device__ __forceinline__ uint32_t smem_u32(const void* p) {
    uint32_t a;
    asm("{ .reg .u64 t; cvta.to.shared.u64 t, %1; cvt.u32.u64 %0, t; }" : "=r"(a) : "l"(p));
    return a;
}
__device__ __forceinline__ void mma16816(float* d, const uint32_t* a, const uint32_t* b) {
    asm volatile(
        "mma.sync.aligned.m16n8k16.row.col.f32.bf16.bf16.f32 "
        "{%0,%1,%2,%3}, {%4,%5,%6,%7}, {%8,%9}, {%0,%1,%2,%3};"
        : "+f"(d[0]), "+f"(d[1]), "+f"(d[2]), "+f"(d[3])
        : "r"(a[0]), "r"(a[1]), "r"(a[2]), "r"(a[3]), "r"(b[0]), "r"(b[1]));
}
__device__ __forceinline__ void ldsm4(uint32_t* r, uint32_t addr) {
    asm volatile("ldmatrix.sync.aligned.m8n8.x4.shared.b16 {%0,%1,%2,%3}, [%4];"
                 : "=r"(r[0]), "=r"(r[1]), "=r"(r[2]), "=r"(r[3]) : "r"(addr));
}
__device__ __forceinline__ void cpasync16(uint32_t dst, const void* src) {
    asm volatile("cp.async.cg.shared.global [%0], [%1], 16;" :: "r"(dst), "l"(src));
}
__device__ __forceinline__ void cp_commit() {
    asm volatile("cp.async.commit_group;" ::: "memory");
}
template <int N>
__device__ __forceinline__ void cp_wait() {
    asm volatile("cp.async.wait_group %0;" :: "n"(N) : "memory");
}

// ---------------------------------------------------------------------------
// bf16 split helpers
// ---------------------------------------------------------------------------
__device__ __forceinline__ void split_bf16(float f, __nv_bfloat16& hi, __nv_bfloat16& lo) {
    hi = __float2bfloat16(f);
    lo = __float2bfloat16(f - __bfloat162float(hi));
}

// ---------------------------------------------------------------------------
// RoPE tables
// ---------------------------------------------------------------------------
__global__ void rope_tables_kernel() {
    int idx = blockIdx.x * blockDim.x + threadIdx.x;
    if (idx >= MM * HALF_D) return;
    int m = idx / HALF_D;
    int i = idx % HALF_D;
    double theta_d = pow(10000.0, -2.0 * ((double)i - 1.0) / (double)DD);
    float ang = (float)m * (float)theta_d;
    g_cos[idx] = cosf(ang);
    g_sin[idx] = sinf(ang);
}

// ---------------------------------------------------------------------------
// fp32 -> 3-segment bf16 split (A-side [hi,lo,hi]) for x
// ---------------------------------------------------------------------------
__global__ void cvt3_x_kernel(const float* __restrict__ src, __nv_bfloat16* __restrict__ dst) {
    long idx = (long)blockIdx.x * blockDim.x + threadIdx.x;
    if (idx >= (long)ROWS * DD) return;
    long row = idx / DD;
    int k = (int)(idx % DD);
    __nv_bfloat16 hi, lo;
    split_bf16(src[idx], hi, lo);
    __nv_bfloat16* r = dst + row * (long)K3P;
    r[k] = hi;
    r[DD + k] = lo;
    r[2 * DD + k] = hi;
}

// ---------------------------------------------------------------------------
// All three weights -> B-side split [hi,hi,lo] in one launch (z selects w)
// ---------------------------------------------------------------------------
__global__ void cvt3_w_kernel(const float* __restrict__ wq, const float* __restrict__ wk,
                              const float* __restrict__ wv, __nv_bfloat16* __restrict__ dst) {
    long idx = (long)blockIdx.x * blockDim.x + threadIdx.x;
    if (idx >= (long)DD * DD) return;
    const float* src = blockIdx.z == 0 ? wq : (blockIdx.z == 1 ? wk : wv);
    long row = idx / DD;
    int k = (int)(idx % DD);
    __nv_bfloat16 hi, lo;
    split_bf16(src[idx], hi, lo);
    __nv_bfloat16* r = dst + ((long)blockIdx.z * DD + row) * (long)K3P;
    r[k] = hi;
    r[DD + k] = hi;
    r[2 * DD + k] = lo;
}

// ---------------------------------------------------------------------------
// V [b*MM + k][n] -> V3T [b*DD + n][seg*MM + k]  (transpose + split, B-side)
// ---------------------------------------------------------------------------
__global__ void vT_cvt_kernel(const float* __restrict__ V, __nv_bfloat16* __restrict__ V3T) {
    __shared__ float ts[32][33];
    int b = blockIdx.z;
    int n0 = blockIdx.x * 32, k0 = blockIdx.y * 32;
    int tx = threadIdx.x, ty = threadIdx.y;  // 32 x 8
#pragma unroll
    for (int i = 0; i < 4; i++) {
        int k = k0 + ty + i * 8;
        ts[ty + i * 8][tx] = V[((long)(b * MM + k)) * DD + n0 + tx];
    }
    __syncthreads();
#pragma unroll
    for (int i = 0; i < 4; i++) {
        int n = n0 + ty + i * 8;
        float f = ts[tx][ty + i * 8];
        __nv_bfloat16 hi, lo;
        split_bf16(f, hi, lo);
        __nv_bfloat16* r = V3T + ((long)(b * DD + n)) * K3S;
        int k = k0 + tx;
        r[k] = hi;
        r[MM + k] = hi;
        r[2 * MM + k] = lo;
    }
}

// ---------------------------------------------------------------------------
// Row softmax (len MM) fused with A-side split conversion
// ---------------------------------------------------------------------------
__global__ void __launch_bounds__(256) softmax_cvt_kernel(const float* __restrict__ S,
                                                          __nv_bfloat16* __restrict__ S3) {
    __shared__ float red[256];
    long row = blockIdx.x;
    const float4* p = reinterpret_cast<const float4*>(S + row * (long)MM);
    int t = threadIdx.x;
    float4 v0 = p[t];
    float4 v1 = p[t + 256];

    float mx = fmaxf(fmaxf(fmaxf(v0.x, v0.y), fmaxf(v0.z, v0.w)),
                     fmaxf(fmaxf(v1.x, v1.y), fmaxf(v1.z, v1.w)));
    red[t] = mx;
    __syncthreads();
    for (int s = 128; s > 0; s >>= 1) {
        if (t < s) red[t] = fmaxf(red[t], red[t + s]);
        __syncthreads();
    }
    mx = red[0];
    __syncthreads();

    v0.x = expf(v0.x - mx); v0.y = expf(v0.y - mx);
    v0.z = expf(v0.z - mx); v0.w = expf(v0.w - mx);
    v1.x = expf(v1.x - mx); v1.y = expf(v1.y - mx);
    v1.z = expf(v1.z - mx); v1.w = expf(v1.w - mx);

    float sum = (v0.x + v0.y + v0.z + v0.w) + (v1.x + v1.y + v1.z + v1.w);
    red[t] = sum;
    __syncthreads();
    for (int s = 128; s > 0; s >>= 1) {
        if (t < s) red[t] += red[t + s];
        __syncthreads();
    }
    float inv = 1.0f / red[0];
    __syncthreads();

    __nv_bfloat16* r = S3 + row * (long)K3S;
    float f[8] = {v0.x * inv, v0.y * inv, v0.z * inv, v0.w * inv,
                  v1.x * inv, v1.y * inv, v1.z * inv, v1.w * inv};
    int cb[2] = {4 * t, 1024 + 4 * t};
#pragma unroll
    for (int h = 0; h < 2; h++) {
#pragma unroll
        for (int j = 0; j < 4; j += 2) {
            __nv_bfloat16 h0, l0, h1, l1;
            split_bf16(f[h * 4 + j], h0, l0);
            split_bf16(f[h * 4 + j + 1], h1, l1);
            int k = cb[h] + j;
            *reinterpret_cast<__nv_bfloat162*>(r + k)          = __halves2bfloat162(h0, h1);
            *reinterpret_cast<__nv_bfloat162*>(r + MM + k)     = __halves2bfloat162(l0, l1);  // lo (A-side)
            *reinterpret_cast<__nv_bfloat162*>(r + 2 * MM + k) = __halves2bfloat162(h0, h1);
        }
    }
}

// ---------------------------------------------------------------------------
// mma.sync bf16 GEMM (NT, both operands K-major), 128x128 CTA tile, BK=64,
// 3-stage cp.async pipeline, XOR-swizzled smem.
// 4 warps (2M x 2N), 64x64 warp tile. Register fragments double-buffered:
// LDSM for k-step ks+1 issues before the 32 HMMA of step ks, so ldmatrix
// latency hides under tensor-pipe issue.
//   EPI=0: C[m,n] = alpha * A x B^T   (fp32 store)
//   EPI=1: merged QKV projection epilogue with fused RoPE + split
// ---------------------------------------------------------------------------
#define BKC 64                     // K per chunk (bf16 elems)
#define TILE_BYTES (128 * BKC * 2) // 16 KB per operand tile
#define GEMM_SMEM (6 * TILE_BYTES) // 3 stages x (A+B) = 96 KB

template <int EPI>
__global__ void __launch_bounds__(128, 2) mma_gemm_kernel(
    const __nv_bfloat16* __restrict__ A, const __nv_bfloat16* __restrict__ B,
    float* __restrict__ C, int K3, int ldc, long sA, long sB, long sC, float alpha)
{
    extern __shared__ char smem[];
    const uint32_t sb = smem_u32(smem);
    const int tid = threadIdx.x;
    const int wid = tid >> 5, lane = tid & 31;
    const int wm = wid & 1;          // warp M index (x64 rows)
    const int wn = wid >> 1;         // warp N index (x64 cols)

    const long row0 = (long)blockIdx.y * 128;
    const long col0 = (long)blockIdx.x * 128;
    const __nv_bfloat16* Abase = A + blockIdx.z * sA + row0 * K3;
    const __nv_bfloat16* Bbase = B + blockIdx.z * sB + col0 * K3;
    float* Cbase = C + blockIdx.z * sC;

    const int ldRow = tid >> 3;      // rows 0..15 (+16*i)
    const int ldC = tid & 7;         // 16B chunk within 128B row

    float acc[4][8][4];
#pragma unroll
    for (int i = 0; i < 4; i++)
#pragma unroll
        for (int j = 0; j < 8; j++)
#pragma unroll
            for (int q = 0; q < 4; q++) acc[i][j][q] = 0.0f;

    const int nch = K3 >> 6;

    auto load_tile = [&](int ch, int buf) {
        const long k0 = (long)ch << 6;
        const uint32_t sbA = sb + buf * 2 * TILE_BYTES;
        const uint32_t sbB = sbA + TILE_BYTES;
#pragma unroll
        for (int i = 0; i < 8; i++) {
            int row = ldRow + i * 16;
            int c = ldC;
            uint32_t off = ((uint32_t)row * 8u + (uint32_t)(c ^ (row & 7))) * 16u;
            cpasync16(sbA + off, Abase + (long)row * K3 + k0 + c * 8);
            cpasync16(sbB + off, Bbase + (long)row * K3 + k0 + c * 8);
        }
    };

    // precomputed ldmatrix row/col components (swizzle applied per-step)
    const int lrow = lane & 15;
    const int lcol = lane >> 4;

    load_tile(0, 0);
    cp_commit();
    load_tile(1, 1);
    cp_commit();

    for (int ch = 0; ch < nch; ch++) {
        if (ch + 2 < nch) {
            load_tile(ch + 2, (ch + 2) % 3);
            cp_commit();
            cp_wait<2>();
        } else if (ch + 1 < nch) {
            cp_wait<1>();
        } else {
            cp_wait<0>();
        }
        __syncthreads();

        const uint32_t sbA = sb + (ch % 3) * 2 * TILE_BYTES;
        const uint32_t sbB = sbA + TILE_BYTES;

        uint32_t fa[2][4][4];
        uint32_t fb[2][8][2];

        auto load_frags = [&](int ks, int pb) {
#pragma unroll
            for (int mt = 0; mt < 4; mt++) {
                int row = wm * 64 + mt * 16 + lrow;
                int c = 2 * ks + lcol;
                uint32_t addr = sbA + ((uint32_t)row * 8u + (uint32_t)(c ^ (row & 7))) * 16u;
                ldsm4(fa[pb][mt], addr);
            }
#pragma unroll
            for (int p = 0; p < 4; p++) {
                int row = wn * 64 + p * 16 + lrow;
                int c = 2 * ks + lcol;
                uint32_t addr = sbB + ((uint32_t)row * 8u + (uint32_t)(c ^ (row & 7))) * 16u;
                uint32_t r[4];
                ldsm4(r, addr);
                fb[pb][2 * p][0] = r[0]; fb[pb][2 * p][1] = r[2];
                fb[pb][2 * p + 1][0] = r[1]; fb[pb][2 * p + 1][1] = r[3];
            }
        };

        load_frags(0, 0);
#pragma unroll
        for (int ks = 0; ks < 4; ks++) {             // 4 k16 steps in BK=64
            if (ks < 3) load_frags(ks + 1, (ks + 1) & 1);
#pragma unroll
            for (int mt = 0; mt < 4; mt++)
#pragma unroll
                for (int nt = 0; nt < 8; nt++)
                    mma16816(acc[mt][nt], fa[ks & 1][mt], fb[ks & 1][nt]);
        }
        __syncthreads();
    }

    // ---- epilogue ----
    const int g = lane >> 2, tg = lane & 3;
    if (EPI == 0) {
#pragma unroll
        for (int mt = 0; mt < 4; mt++) {
            long r0 = row0 + wm * 64 + mt * 16 + g;
#pragma unroll
            for (int nt = 0; nt < 8; nt++) {
                long cc = col0 + wn * 64 + nt * 8 + tg * 2;
                float2 v0 = make_float2(alpha * acc[mt][nt][0], alpha * acc[mt][nt][1]);
                float2 v1 = make_float2(alpha * acc[mt][nt][2], alpha * acc[mt][nt][3]);
                *reinterpret_cast<float2*>(Cbase + r0 * ldc + cc) = v0;
                *reinterpret_cast<float2*>(Cbase + (r0 + 8) * ldc + cc) = v1;
            }
        }
    } else {
        // merged QKV epilogue. n in [0,3072): Q | K | V
        const int nbase = (int)col0 + wn * 64 + tg * 2;
#pragma unroll
        for (int mt = 0; mt < 4; mt++) {
            long r0 = row0 + wm * 64 + mt * 16 + g;   // global row (+8 for second half)
#pragma unroll
            for (int nt = 0; nt < 8; nt++) {
                int n = nbase + nt * 8;
                if (n < 2048) {
                    // RoPE + 3-seg split
                    int k = n & 1023;                 // col within Q or K block
                    int pidx = k >> 1;
#pragma unroll
                    for (int h = 0; h < 2; h++) {
                        long r = r0 + h * 8;
                        int m = (int)(r & (MM - 1));
                        float c = g_cos[(size_t)m * HALF_D + pidx];
                        float s = g_sin[(size_t)m * HALF_D + pidx];
                        float e = acc[mt][nt][2 * h], o = acc[mt][nt][2 * h + 1];
                        float re = e * c + o * s;
                        float ro = -e * s + o * c;
                        __nv_bfloat16 he, le, ho, lo;
                        split_bf16(re, he, le);
                        split_bf16(ro, ho, lo);
                        __nv_bfloat16* dst = (n < 1024 ? g_Q3 : g_K3) + r * (long)K3P + k;
                        __nv_bfloat162 hi2 = __halves2bfloat162(he, ho);
                        __nv_bfloat162 lo2 = __halves2bfloat162(le, lo);
                        // Q (A-side): [hi,lo,hi]   K (B-side): [hi,hi,lo]
                        *reinterpret_cast<__nv_bfloat162*>(dst) = hi2;
                        *reinterpret_cast<__nv_bfloat162*>(dst + DD) = (n < 1024) ? lo2 : hi2;
                        *reinterpret_cast<__nv_bfloat162*>(dst + 2 * DD) = (n < 1024) ? hi2 : lo2;
                    }
                } else {
                    int k = n - 2048;
                    float2 v0 = make_float2(acc[mt][nt][0], acc[mt][nt][1]);
                    float2 v1 = make_float2(acc[mt][nt][2], acc[mt][nt][3]);
                    *reinterpret_cast<float2*>(g_Vf + r0 * DD + k) = v0;
                    *reinterpret_cast<float2*>(g_Vf + (r0 + 8) * DD + k) = v1;
                }
            }
        }
    }
}

// ---------------------------------------------------------------------------
// Launch.  Order keeps the scores GEMM at launch index 5 for the ncu capture.
// ---------------------------------------------------------------------------
extern "C" void kernel_launch(void* const* d_in, const int* in_sizes, int n_in,
                              void* d_out, int out_size) {
    (void)in_sizes; (void)n_in; (void)out_size;
    const float* x  = (const float*)d_in[0];
    const float* wq = (const float*)d_in[1];
    const float* wk = (const float*)d_in[2];
    const float* wv = (const float*)d_in[3];
    float* out = (float*)d_out;

    __nv_bfloat16 *x3, *w3, *Q3, *K3, *V3T, *S3;
    float *Vf, *Sf;
    cudaGetSymbolAddress((void**)&x3, g_x3);
    cudaGetSymbolAddress((void**)&w3, g_w3);
    cudaGetSymbolAddress((void**)&Vf, g_Vf);
    cudaGetSymbolAddress((void**)&Q3, g_Q3);
    cudaGetSymbolAddress((void**)&K3, g_K3);
    cudaGetSymbolAddress((void**)&V3T, g_V3T);
    cudaGetSymbolAddress((void**)&Sf, g_Sf);
    cudaGetSymbolAddress((void**)&S3, g_S3);

    cudaFuncSetAttribute(mma_gemm_kernel<0>, cudaFuncAttributeMaxDynamicSharedMemorySize, GEMM_SMEM);
    cudaFuncSetAttribute(mma_gemm_kernel<1>, cudaFuncAttributeMaxDynamicSharedMemorySize, GEMM_SMEM);

    // 0: RoPE tables
    rope_tables_kernel<<<(MM * HALF_D + 255) / 256, 256>>>();
    // 1: x -> split
    cvt3_x_kernel<<<(int)(((long)ROWS * DD + 255) / 256), 256>>>(x, x3);
    // 2: all weights -> split
    dim3 gW((DD * DD + 255) / 256, 1, 3);
    cvt3_w_kernel<<<gW, 256>>>(wq, wk, wv, w3);

    // 3: Merged QKV projection with fused RoPE/split epilogue
    dim3 gProj(3 * DD / 128, ROWS / 128, 1);
    mma_gemm_kernel<1><<<gProj, 128, GEMM_SMEM>>>(x3, w3, nullptr, K3P, 0, 0, 0, 0, 1.0f);

    // 4: V transpose + split
    dim3 gV(DD / 32, MM / 32, BB);
    vT_cvt_kernel<<<gV, dim3(32, 8)>>>(Vf, V3T);

    // 5: scores = Qr @ Kr^T / 32   <- ncu capture target
    dim3 gScore(MM / 128, MM / 128, BB);
    mma_gemm_kernel<0><<<gScore, 128, GEMM_SMEM>>>(Q3, K3, Sf, K3P, MM,
                                                   (long)MM * K3P, (long)MM * K3P,
                                                   (long)MM * MM, 0.03125f);

    // 6: softmax + split
    softmax_cvt_kernel<<<BB * MM, 256>>>(Sf, S3);

    // 7: out = attn @ V
    dim3 gOut(DD / 128, MM / 128, BB);
    mma_gemm_kernel<0><<<gOut, 128, GEMM_SMEM>>>(S3, V3T, out, K3S, DD,
                                                 (long)MM * K3S, (long)DD * K3S,
                                                 (long)MM * DD, 1.0f);
}